// round 3
// baseline (speedup 1.0000x reference)
#include <cuda_runtime.h>
#include <cuda_fp16.h>
#include <mma.h>
#include <math.h>

using namespace nvcuda;

// Problem sizes (fixed by the reference)
#define M_TOTAL 32768
#define K_TOTAL 2048
#define N_TOTAL 2048

// Tile config
#define BM 128          // rows per CTA
#define BN 64           // n-tile (reduced immediately into running logsumexp)
#define BK 64           // k-chunk
#define LDX 72          // smem leading dim for x tile (halves)
#define LDW 72          // smem leading dim for W tile (halves)
#define LDY 72          // smem leading dim for y tile (floats)

#define NTHREADS 256    // 8 warps: 4 (M) x 2 (N)

__global__ __launch_bounds__(NTHREADS, 1)
void fused_gemm_lse_kernel(const float* __restrict__ x,
                           const float* __restrict__ W,
                           const float* __restrict__ bias,
                           float* __restrict__ out)
{
    // Union: during GEMM k-loop smem holds x-tile + W-tile; during reduction it
    // holds the fp32 y-tile. max(18432+9216, 36864) = 36864 bytes (< 48KB static).
    __shared__ __align__(16) unsigned char smem_raw[BM * LDY * 4];
    __half* xs    = reinterpret_cast<__half*>(smem_raw);                  // BM x LDX
    __half* ws    = reinterpret_cast<__half*>(smem_raw + BM * LDX * 2);   // BK x LDW
    float*  ytile = reinterpret_cast<float*>(smem_raw);                   // BM x LDY

    const int tid    = threadIdx.x;
    const int wid    = tid >> 5;
    const int warp_m = wid >> 1;   // 0..3  -> 32-row slab
    const int warp_n = wid & 1;    // 0..1  -> 32-col slab
    const int r0     = blockIdx.x * BM;

    // Reduction assignment: 2 threads per row. Thread t handles row (t>>1),
    // column half (t&1)*32 .. +31. Partner is t^1 (adjacent lane -> shfl works).
    const int red_row  = tid >> 1;
    const int red_half = tid & 1;

    // Per-thread running logsumexp partial state (max + sum over owned columns).
    float run_m = -INFINITY;
    float run_s = 0.0f;

    for (int nt = 0; nt < N_TOTAL / BN; ++nt) {
        wmma::fragment<wmma::accumulator, 16, 16, 16, float> acc[2][2];
        #pragma unroll
        for (int mi = 0; mi < 2; ++mi)
            #pragma unroll
            for (int ni = 0; ni < 2; ++ni)
                wmma::fill_fragment(acc[mi][ni], 0.0f);

        for (int kt = 0; kt < K_TOTAL / BK; ++kt) {
            __syncthreads();  // smem free (prev compute done / ytile reduce done)

            // Load x tile: BM x BK floats. float4 = 4 elems -> 2048 vec loads,
            // 8 per thread. Convert f32 -> f16 while staging.
            #pragma unroll
            for (int it = 0; it < 8; ++it) {
                int t   = tid + it * NTHREADS;
                int row = t >> 4;        // 16 float4-groups per 64-col row
                int c4  = t & 15;
                float4 v = *reinterpret_cast<const float4*>(
                    x + (size_t)(r0 + row) * K_TOTAL + kt * BK + c4 * 4);
                __half2* dst = reinterpret_cast<__half2*>(xs + row * LDX + c4 * 4);
                dst[0] = __floats2half2_rn(v.x, v.y);
                dst[1] = __floats2half2_rn(v.z, v.w);
            }
            // Load W tile: BK x BN floats -> 1024 vec loads, 4 per thread.
            #pragma unroll
            for (int it = 0; it < 4; ++it) {
                int t   = tid + it * NTHREADS;
                int row = t >> 4;
                int c4  = t & 15;
                float4 v = *reinterpret_cast<const float4*>(
                    W + (size_t)(kt * BK + row) * N_TOTAL + nt * BN + c4 * 4);
                __half2* dst = reinterpret_cast<__half2*>(ws + row * LDW + c4 * 4);
                dst[0] = __floats2half2_rn(v.x, v.y);
                dst[1] = __floats2half2_rn(v.z, v.w);
            }
            __syncthreads();

            #pragma unroll
            for (int ks = 0; ks < BK / 16; ++ks) {
                wmma::fragment<wmma::matrix_a, 16, 16, 16, half, wmma::row_major> af[2];
                wmma::fragment<wmma::matrix_b, 16, 16, 16, half, wmma::row_major> bf[2];
                #pragma unroll
                for (int mi = 0; mi < 2; ++mi)
                    wmma::load_matrix_sync(af[mi],
                        xs + (warp_m * 32 + mi * 16) * LDX + ks * 16, LDX);
                #pragma unroll
                for (int ni = 0; ni < 2; ++ni)
                    wmma::load_matrix_sync(bf[ni],
                        ws + (ks * 16) * LDW + warp_n * 32 + ni * 16, LDW);
                #pragma unroll
                for (int mi = 0; mi < 2; ++mi)
                    #pragma unroll
                    for (int ni = 0; ni < 2; ++ni)
                        wmma::mma_sync(acc[mi][ni], af[mi], bf[ni], acc[mi][ni]);
            }
        }
        __syncthreads();  // done reading xs/ws; safe to overwrite with ytile

        // Spill fp32 accumulators to smem for the row reduction
        #pragma unroll
        for (int mi = 0; mi < 2; ++mi)
            #pragma unroll
            for (int ni = 0; ni < 2; ++ni)
                wmma::store_matrix_sync(
                    ytile + (warp_m * 32 + mi * 16) * LDY + warp_n * 32 + ni * 16,
                    acc[mi][ni], LDY, wmma::mem_row_major);
        __syncthreads();

        // Online logsumexp fold for this 128x64 tile.
        // All 256 threads: 2 per row, 32 columns each.
        {
            const float* yr = ytile + red_row * LDY + red_half * 32;
            const float* bptr = bias + nt * BN + red_half * 32;

            float v[32];
            float tm = -INFINITY;
            #pragma unroll
            for (int c = 0; c < 32; ++c) {
                v[c] = yr[c] + __ldg(bptr + c);
                tm = fmaxf(tm, v[c]);
            }
            float nm = fmaxf(run_m, tm);
            float s  = run_s * __expf(run_m - nm);  // first tile: 0 * exp(-inf) = 0
            #pragma unroll
            for (int c = 0; c < 32; ++c)
                s += __expf(v[c] - nm);
            run_m = nm;
            run_s = s;
        }
        // smem reuse protected by the __syncthreads() at top of next k-loop
    }

    // Combine the two half-row partials (lanes t and t^1 are shfl partners).
    {
        float om = __shfl_xor_sync(0xFFFFFFFFu, run_m, 1);
        float os = __shfl_xor_sync(0xFFFFFFFFu, run_s, 1);
        float nm = fmaxf(run_m, om);
        float s  = run_s * __expf(run_m - nm) + os * __expf(om - nm);

        if (red_half == 0) {
            // Epilogue: logsumexp -> leaky_relu x2 -> exact GELU x2
            float z = nm + logf(s);
            z = (z > 0.0f) ? z : 0.01f * z;
            z = (z > 0.0f) ? z : 0.01f * z;
            z = 0.5f * z * (1.0f + erff(z * 0.70710678118654752f));
            z = 0.5f * z * (1.0f + erff(z * 0.70710678118654752f));
            out[r0 + red_row] = z;
        }
    }
}

extern "C" void kernel_launch(void* const* d_in, const int* in_sizes, int n_in,
                              void* d_out, int out_size)
{
    const float* x    = (const float*)d_in[0];   // (M, K) f32 (harness-widened fp16)
    const float* W    = (const float*)d_in[1];   // (K, N) f32
    const float* bias = (const float*)d_in[2];   // (N,)   f32
    float* out        = (float*)d_out;           // (M, 1) f32

    dim3 grid(M_TOTAL / BM);   // 256 CTAs
    dim3 block(NTHREADS);
    fused_gemm_lse_kernel<<<grid, block>>>(x, W, bias, out);
}

// round 4
// speedup vs baseline: 2.2880x; 2.2880x over previous
#include <cuda_runtime.h>
#include <cuda_fp16.h>
#include <math.h>

// Problem sizes (fixed)
#define M_TOTAL 32768
#define K_TOTAL 2048
#define N_TOTAL 2048

// GEMM tiling
#define BM 128
#define BN 128
#define BK 32
#define NK (K_TOTAL / BK)   // 64 k-chunks
#define NT (N_TOTAL / BN)   // 16 n-tiles
#define THREADS 512         // 16 warps: 4 (M) x 4 (N)

#define LDX 40              // smem halves per x row (pad -> conflict-free ldmatrix)
#define LDW 136             // smem halves per W row

// fp16 scratch (device globals: allocation-free per harness rules)
__device__ __half g_x16[(size_t)M_TOTAL * K_TOTAL];   // 128 MB
__device__ __half g_w16[(size_t)K_TOTAL * N_TOTAL];   // 8 MB

// ---------------- conversion kernels (f32 -> f16), one float4 per thread ----
__global__ void conv_x_kernel(const float* __restrict__ src) {
    size_t i = (size_t)blockIdx.x * blockDim.x + threadIdx.x;    // float4 index
    float4 v = reinterpret_cast<const float4*>(src)[i];
    __half2 h0 = __floats2half2_rn(v.x, v.y);
    __half2 h1 = __floats2half2_rn(v.z, v.w);
    uint2 o;
    o.x = *reinterpret_cast<unsigned*>(&h0);
    o.y = *reinterpret_cast<unsigned*>(&h1);
    reinterpret_cast<uint2*>(g_x16)[i] = o;
}
__global__ void conv_w_kernel(const float* __restrict__ src) {
    size_t i = (size_t)blockIdx.x * blockDim.x + threadIdx.x;
    float4 v = reinterpret_cast<const float4*>(src)[i];
    __half2 h0 = __floats2half2_rn(v.x, v.y);
    __half2 h1 = __floats2half2_rn(v.z, v.w);
    uint2 o;
    o.x = *reinterpret_cast<unsigned*>(&h0);
    o.y = *reinterpret_cast<unsigned*>(&h1);
    reinterpret_cast<uint2*>(g_w16)[i] = o;
}

// ---------------- helpers ---------------------------------------------------
__device__ __forceinline__ unsigned smem_u32(const void* p) {
    return (unsigned)__cvta_generic_to_shared(p);
}
__device__ __forceinline__ void cp_async16(unsigned dst, const void* src) {
    asm volatile("cp.async.cg.shared.global [%0], [%1], 16;\n" :: "r"(dst), "l"(src));
}
__device__ __forceinline__ void cp_commit() {
    asm volatile("cp.async.commit_group;\n");
}
__device__ __forceinline__ void cp_wait0() {
    asm volatile("cp.async.wait_group 0;\n");
}

// ---------------- fused GEMM + online logsumexp -----------------------------
__global__ __launch_bounds__(THREADS, 1)
void gemm_lse_kernel(const float* __restrict__ bias, float* __restrict__ out)
{
    __shared__ __align__(16) __half xs[2][BM * LDX];   // 20.0 KB
    __shared__ __align__(16) __half ws[2][BK * LDW];   // 17.0 KB
    __shared__ __align__(16) float2 comb[4][BM];       //  4.0 KB

    const int tid  = threadIdx.x;
    const int lane = tid & 31;
    const int wid  = tid >> 5;
    const int wm   = wid >> 2;          // 0..3 : 32-row slab
    const int wn   = wid & 3;           // 0..3 : 32-col slab
    const int r0   = blockIdx.x * BM;
    const int qr   = lane >> 2;         // 0..7
    const int qc   = lane & 3;          // 0..3

    // cp.async assignments (one 16B chunk per thread per tile)
    const int xa_row = tid >> 2,  xa_c = (tid & 3) << 3;    // x: 128 rows x 4 chunks
    const int wa_row = tid >> 4,  wa_c = (tid & 15) << 3;   // W:  32 rows x 16 chunks
    const __half* gx_base = g_x16 + (size_t)(r0 + xa_row) * K_TOTAL + xa_c;
    const unsigned xs_dst[2] = { smem_u32(&xs[0][xa_row * LDX + xa_c]),
                                 smem_u32(&xs[1][xa_row * LDX + xa_c]) };
    const unsigned ws_dst[2] = { smem_u32(&ws[0][wa_row * LDW + wa_c]),
                                 smem_u32(&ws[1][wa_row * LDW + wa_c]) };

    // ldmatrix per-lane addressing (16x16 tiles)
    const int a_row = lane & 15;
    const int a_c8  = (lane >> 4) << 3;

    // Running LSE state: 4 rows per thread: [mi][h] -> row wm*32 + mi*16 + h*8 + qr
    float run_m[2][2], run_s[2][2];
    #pragma unroll
    for (int a = 0; a < 2; ++a)
        #pragma unroll
        for (int b = 0; b < 2; ++b) { run_m[a][b] = -INFINITY; run_s[a][b] = 0.0f; }

    for (int nt = 0; nt < NT; ++nt) {
        float acc[2][4][4];
        #pragma unroll
        for (int mi = 0; mi < 2; ++mi)
            #pragma unroll
            for (int j = 0; j < 4; ++j)
                #pragma unroll
                for (int c = 0; c < 4; ++c) acc[mi][j][c] = 0.0f;

        const __half* gw_base = g_w16 + (size_t)wa_row * N_TOTAL + nt * BN + wa_c;

        // preload stage 0
        cp_async16(xs_dst[0], gx_base);
        cp_async16(ws_dst[0], gw_base);
        cp_commit();

        for (int kt = 0; kt < NK; ++kt) {
            cp_wait0();
            __syncthreads();
            if (kt + 1 < NK) {
                const int nb = (kt + 1) & 1;
                cp_async16(xs_dst[nb], gx_base + (kt + 1) * BK);
                cp_async16(ws_dst[nb], gw_base + (size_t)(kt + 1) * BK * N_TOTAL);
                cp_commit();
            }
            const int cur = kt & 1;

            #pragma unroll
            for (int ks = 0; ks < 2; ++ks) {
                unsigned a[2][4];
                #pragma unroll
                for (int mi = 0; mi < 2; ++mi) {
                    unsigned addr = smem_u32(
                        &xs[cur][(wm * 32 + mi * 16 + a_row) * LDX + ks * 16 + a_c8]);
                    asm volatile(
                        "ldmatrix.sync.aligned.m8n8.x4.shared.b16 {%0,%1,%2,%3}, [%4];\n"
                        : "=r"(a[mi][0]), "=r"(a[mi][1]), "=r"(a[mi][2]), "=r"(a[mi][3])
                        : "r"(addr));
                }
                unsigned b[2][4];
                #pragma unroll
                for (int nb2 = 0; nb2 < 2; ++nb2) {
                    unsigned addr = smem_u32(
                        &ws[cur][(ks * 16 + a_row) * LDW + wn * 32 + nb2 * 16 + a_c8]);
                    asm volatile(
                        "ldmatrix.sync.aligned.m8n8.x4.trans.shared.b16 {%0,%1,%2,%3}, [%4];\n"
                        : "=r"(b[nb2][0]), "=r"(b[nb2][1]), "=r"(b[nb2][2]), "=r"(b[nb2][3])
                        : "r"(addr));
                }
                #pragma unroll
                for (int mi = 0; mi < 2; ++mi)
                    #pragma unroll
                    for (int j = 0; j < 4; ++j) {
                        unsigned b0 = b[j >> 1][(j & 1) * 2];
                        unsigned b1 = b[j >> 1][(j & 1) * 2 + 1];
                        asm volatile(
                            "mma.sync.aligned.m16n8k16.row.col.f32.f16.f16.f32 "
                            "{%0,%1,%2,%3}, {%4,%5,%6,%7}, {%8,%9}, {%0,%1,%2,%3};\n"
                            : "+f"(acc[mi][j][0]), "+f"(acc[mi][j][1]),
                              "+f"(acc[mi][j][2]), "+f"(acc[mi][j][3])
                            : "r"(a[mi][0]), "r"(a[mi][1]), "r"(a[mi][2]), "r"(a[mi][3]),
                              "r"(b0), "r"(b1));
                    }
            }
        }

        // --- per-n-tile online LSE fold (all in registers + quad shuffles) ---
        // Thread's columns: global col = nt*BN + wn*32 + j*8 + qc*2 + {0,1}
        float2 bj[4];
        {
            const float2* bb = reinterpret_cast<const float2*>(
                bias + nt * BN + wn * 32 + qc * 2);
            #pragma unroll
            for (int j = 0; j < 4; ++j) bj[j] = __ldg(&bb[j * 4]);
        }
        #pragma unroll
        for (int mi = 0; mi < 2; ++mi)
            #pragma unroll
            for (int h = 0; h < 2; ++h) {
                float v[8];
                #pragma unroll
                for (int j = 0; j < 4; ++j) {
                    v[j * 2]     = acc[mi][j][h * 2]     + bj[j].x;
                    v[j * 2 + 1] = acc[mi][j][h * 2 + 1] + bj[j].y;
                }
                float tm = v[0];
                #pragma unroll
                for (int c = 1; c < 8; ++c) tm = fmaxf(tm, v[c]);
                tm = fmaxf(tm, __shfl_xor_sync(0xFFFFFFFFu, tm, 1));
                tm = fmaxf(tm, __shfl_xor_sync(0xFFFFFFFFu, tm, 2));
                float s = 0.0f;
                #pragma unroll
                for (int c = 0; c < 8; ++c) s += __expf(v[c] - tm);
                s += __shfl_xor_sync(0xFFFFFFFFu, s, 1);
                s += __shfl_xor_sync(0xFFFFFFFFu, s, 2);
                // merge (row slice over this warp's 32 cols) into running state
                float nm = fmaxf(run_m[mi][h], tm);
                run_s[mi][h] = run_s[mi][h] * __expf(run_m[mi][h] - nm)
                             + s * __expf(tm - nm);
                run_m[mi][h] = nm;
            }
    }

    // --- cross-warp (n-direction) combine + epilogue ---
    __syncthreads();
    if (qc == 0) {
        #pragma unroll
        for (int mi = 0; mi < 2; ++mi)
            #pragma unroll
            for (int h = 0; h < 2; ++h) {
                int row = wm * 32 + mi * 16 + h * 8 + qr;
                comb[wn][row] = make_float2(run_m[mi][h], run_s[mi][h]);
            }
    }
    __syncthreads();
    if (tid < BM) {
        float m = -INFINITY, s = 0.0f;
        #pragma unroll
        for (int w = 0; w < 4; ++w) {
            float2 p = comb[w][tid];
            float nm = fmaxf(m, p.x);
            s = s * __expf(m - nm) + p.y * __expf(p.x - nm);
            m = nm;
        }
        float z = m + logf(s);
        z = (z > 0.0f) ? z : 0.01f * z;
        z = (z > 0.0f) ? z : 0.01f * z;
        z = 0.5f * z * (1.0f + erff(z * 0.70710678118654752f));
        z = 0.5f * z * (1.0f + erff(z * 0.70710678118654752f));
        out[r0 + tid] = z;
    }
}

extern "C" void kernel_launch(void* const* d_in, const int* in_sizes, int n_in,
                              void* d_out, int out_size)
{
    const float* x    = (const float*)d_in[0];   // (M, K) f32 (widened fp16)
    const float* W    = (const float*)d_in[1];   // (K, N) f32
    const float* bias = (const float*)d_in[2];   // (N,)   f32
    float* out        = (float*)d_out;           // (M, 1) f32

    conv_x_kernel<<<(M_TOTAL * (size_t)K_TOTAL / 4) / 256, 256>>>(x);   // 65536 blocks
    conv_w_kernel<<<(K_TOTAL * (size_t)N_TOTAL / 4) / 256, 256>>>(W);   //  4096 blocks
    gemm_lse_kernel<<<M_TOTAL / BM, THREADS>>>(bias, out);              //   256 CTAs
}

// round 6
// speedup vs baseline: 3.9722x; 1.7361x over previous
#include <cuda_runtime.h>
#include <cuda_fp16.h>
#include <math.h>
#include <stdint.h>

// Problem sizes (fixed)
#define M_TOTAL 32768
#define K_TOTAL 2048
#define N_TOTAL 2048

// Work-unit tiling
#define BM 128
#define BN 64
#define BK 64
#define NKI   (K_TOTAL / BK)     // 32 k-iters per unit
#define NTILES (N_TOTAL / BN)    // 32 n-tiles per panel
#define PANELS (M_TOTAL / BM)    // 256 panels
#define UNITS  (PANELS * NTILES) // 8192 units
#define THREADS 256              // 8 warps: 4 (M) x 2 (N); warp tile 32x32
#define GRID 296                 // 2 CTAs per SM

// SMEM stage layout: xs (128x64 f16 = 16KB) + ws (64x64 f16 = 8KB)
#define XS_BYTES 16384
#define STAGE_BYTES 24576
#define NSTAGE 3
#define COMB_OFF (NSTAGE * STAGE_BYTES)          // 73728
#define SMEM_TOTAL (COMB_OFF + 2 * 128 * 8)      // +2KB comb = 75776

// fp16 scratch + LSE partials
__device__ __half g_x16[(size_t)M_TOTAL * K_TOTAL];    // 128 MB (M,K)
__device__ __half g_wt16[(size_t)N_TOTAL * K_TOTAL];   //   8 MB (N,K) = W^T
__device__ float2 g_part[NTILES][M_TOTAL];             //   8 MB partial (m,s)

// ---------------- conversion kernels ---------------------------------------
__global__ void conv_x_kernel(const float* __restrict__ src) {
    size_t i = (size_t)blockIdx.x * blockDim.x + threadIdx.x;   // float4 index
    float4 v = reinterpret_cast<const float4*>(src)[i];
    __half2 h0 = __floats2half2_rn(v.x, v.y);
    __half2 h1 = __floats2half2_rn(v.z, v.w);
    uint2 o;
    o.x = *reinterpret_cast<unsigned*>(&h0);
    o.y = *reinterpret_cast<unsigned*>(&h1);
    reinterpret_cast<uint2*>(g_x16)[i] = o;
}

// W (K,N) f32 -> Wt (N,K) f16 via 32x32 smem tile transpose
__global__ void conv_wt_kernel(const float* __restrict__ W) {
    __shared__ float t[32][33];
    int n0 = blockIdx.x * 32, k0 = blockIdx.y * 32;
    int tx = threadIdx.x, ty = threadIdx.y;   // 32 x 8
    #pragma unroll
    for (int j = 0; j < 4; ++j)
        t[ty + j * 8][tx] = W[(size_t)(k0 + ty + j * 8) * N_TOTAL + n0 + tx];
    __syncthreads();
    #pragma unroll
    for (int j = 0; j < 4; ++j)
        g_wt16[(size_t)(n0 + ty + j * 8) * K_TOTAL + k0 + tx] =
            __float2half(t[tx][ty + j * 8]);
}

// ---------------- helpers ---------------------------------------------------
__device__ __forceinline__ uint32_t smem_u32(const void* p) {
    return (uint32_t)__cvta_generic_to_shared(p);
}
__device__ __forceinline__ void cp_async16(uint32_t dst, const void* src) {
    asm volatile("cp.async.cg.shared.global [%0], [%1], 16;\n" :: "r"(dst), "l"(src));
}
__device__ __forceinline__ uint32_t sw128(uint32_t off) {   // SW128 xor swizzle
    return off ^ ((off >> 3) & 0x70);
}

// Fill one stage: x 1024 chunks (4/thr) + Wt 512 chunks (2/thr), 16B each
__device__ __forceinline__ void load_stage(uint32_t st, int tid,
                                           int r0, int n0, int kk) {
    #pragma unroll
    for (int i = 0; i < 4; ++i) {
        int c = tid + i * THREADS;
        int row = c >> 3, c16 = c & 7;
        cp_async16(st + sw128(row * 128 + c16 * 16),
                   g_x16 + (size_t)(r0 + row) * K_TOTAL + kk + c16 * 8);
    }
    #pragma unroll
    for (int i = 0; i < 2; ++i) {
        int c = tid + i * THREADS;
        int row = c >> 3, c16 = c & 7;
        cp_async16(st + XS_BYTES + sw128(row * 128 + c16 * 16),
                   g_wt16 + (size_t)(n0 + row) * K_TOTAL + kk + c16 * 8);
    }
}

// ---------------- persistent fused GEMM + per-unit LSE partial --------------
__global__ __launch_bounds__(THREADS, 2)
void gemm_lse_kernel(const float* __restrict__ bias)
{
    extern __shared__ __align__(1024) char smem[];
    const uint32_t sb = smem_u32(smem);
    float2* comb = reinterpret_cast<float2*>(smem + COMB_OFF);   // [2][128]

    const int tid  = threadIdx.x;
    const int lane = tid & 31;
    const int wid  = tid >> 5;
    const int wm   = wid >> 1;          // 0..3 : 32-row slab
    const int wn   = wid & 1;           // 0..1 : 32-col slab
    const int qr   = lane >> 2;         // 0..7
    const int qc   = lane & 3;          // 0..3

    // ldmatrix lane addressing (shared by A and B tiles, both K-major 128B rows)
    const int lm_row = lane & 15;
    const int lm_c16 = (lane >> 4) * 16;   // byte offset of 8-half chunk

    for (int u = blockIdx.x; u < UNITS; u += GRID) {
        const int p  = u >> 5;          // panel
        const int nt = u & 31;          // n-tile
        const int r0 = p * BM;
        const int n0 = nt * BN;

        float acc[2][4][4];
        #pragma unroll
        for (int mi = 0; mi < 2; ++mi)
            #pragma unroll
            for (int j = 0; j < 4; ++j)
                #pragma unroll
                for (int c = 0; c < 4; ++c) acc[mi][j][c] = 0.0f;

        // prologue: stages 0,1
        load_stage(sb + 0 * STAGE_BYTES, tid, r0, n0, 0);
        asm volatile("cp.async.commit_group;\n");
        load_stage(sb + 1 * STAGE_BYTES, tid, r0, n0, BK);
        asm volatile("cp.async.commit_group;\n");

        for (int kt = 0; kt < NKI; ++kt) {
            asm volatile("cp.async.wait_group 1;\n");
            __syncthreads();

            if (kt + 2 < NKI)
                load_stage(sb + ((kt + 2) % NSTAGE) * STAGE_BYTES, tid,
                           r0, n0, (kt + 2) * BK);
            asm volatile("cp.async.commit_group;\n");

            const uint32_t st = sb + (kt % NSTAGE) * STAGE_BYTES;

            #pragma unroll
            for (int ks = 0; ks < 4; ++ks) {
                unsigned a[2][4];
                #pragma unroll
                for (int mi = 0; mi < 2; ++mi) {
                    uint32_t addr = st + sw128(
                        (wm * 32 + mi * 16 + lm_row) * 128 + ks * 32 + lm_c16);
                    asm volatile(
                        "ldmatrix.sync.aligned.m8n8.x4.shared.b16 {%0,%1,%2,%3}, [%4];\n"
                        : "=r"(a[mi][0]), "=r"(a[mi][1]), "=r"(a[mi][2]), "=r"(a[mi][3])
                        : "r"(addr));
                }
                unsigned b[2][4];
                #pragma unroll
                for (int nb = 0; nb < 2; ++nb) {
                    uint32_t addr = st + XS_BYTES + sw128(
                        (wn * 32 + nb * 16 + lm_row) * 128 + ks * 32 + lm_c16);
                    asm volatile(
                        "ldmatrix.sync.aligned.m8n8.x4.shared.b16 {%0,%1,%2,%3}, [%4];\n"
                        : "=r"(b[nb][0]), "=r"(b[nb][1]), "=r"(b[nb][2]), "=r"(b[nb][3])
                        : "r"(addr));
                }
                #pragma unroll
                for (int mi = 0; mi < 2; ++mi)
                    #pragma unroll
                    for (int j = 0; j < 4; ++j) {
                        // n-group j*8: block nb=j>>1; low 8 cols -> {r0,r2}, high -> {r1,r3}
                        unsigned b0 = b[j >> 1][(j & 1)];
                        unsigned b1 = b[j >> 1][(j & 1) + 2];
                        asm volatile(
                            "mma.sync.aligned.m16n8k16.row.col.f32.f16.f16.f32 "
                            "{%0,%1,%2,%3}, {%4,%5,%6,%7}, {%8,%9}, {%0,%1,%2,%3};\n"
                            : "+f"(acc[mi][j][0]), "+f"(acc[mi][j][1]),
                              "+f"(acc[mi][j][2]), "+f"(acc[mi][j][3])
                            : "r"(a[mi][0]), "r"(a[mi][1]), "r"(a[mi][2]), "r"(a[mi][3]),
                              "r"(b0), "r"(b1));
                    }
            }
        }

        // ---- per-unit LSE partial: thread cols = n0 + wn*32 + j*8 + qc*2 ----
        float2 bj[4];
        {
            const float2* bb = reinterpret_cast<const float2*>(
                bias + n0 + wn * 32) + qc;
            #pragma unroll
            for (int j = 0; j < 4; ++j) bj[j] = __ldg(&bb[j * 4]);
        }
        float tile_m[2][2], tile_s[2][2];
        #pragma unroll
        for (int mi = 0; mi < 2; ++mi)
            #pragma unroll
            for (int h = 0; h < 2; ++h) {
                float v[8];
                #pragma unroll
                for (int j = 0; j < 4; ++j) {
                    v[j * 2]     = acc[mi][j][h * 2]     + bj[j].x;
                    v[j * 2 + 1] = acc[mi][j][h * 2 + 1] + bj[j].y;
                }
                float tm = v[0];
                #pragma unroll
                for (int c = 1; c < 8; ++c) tm = fmaxf(tm, v[c]);
                tm = fmaxf(tm, __shfl_xor_sync(0xFFFFFFFFu, tm, 1));
                tm = fmaxf(tm, __shfl_xor_sync(0xFFFFFFFFu, tm, 2));
                float s = 0.0f;
                #pragma unroll
                for (int c = 0; c < 8; ++c) s += __expf(v[c] - tm);
                s += __shfl_xor_sync(0xFFFFFFFFu, s, 1);
                s += __shfl_xor_sync(0xFFFFFFFFu, s, 2);
                tile_m[mi][h] = tm;
                tile_s[mi][h] = s;
            }

        __syncthreads();   // mainloop smem reads done in all warps
        if (qc == 0) {
            #pragma unroll
            for (int mi = 0; mi < 2; ++mi)
                #pragma unroll
                for (int h = 0; h < 2; ++h) {
                    int row = wm * 32 + mi * 16 + h * 8 + qr;
                    comb[wn * 128 + row] =
                        make_float2(tile_m[mi][h], tile_s[mi][h]);
                }
        }
        __syncthreads();
        if (tid < BM) {
            float2 p0 = comb[tid];
            float2 p1 = comb[128 + tid];
            float nm = fmaxf(p0.x, p1.x);
            float s  = p0.y * __expf(p0.x - nm) + p1.y * __expf(p1.x - nm);
            g_part[nt][r0 + tid] = make_float2(nm, s);
        }
        // no trailing sync needed: next unit's stage writes only touch buffers
        // whose reads completed before the first __syncthreads above.
    }
}

// ---------------- final combine: 32 partials per row + activation chain ----
__global__ void combine_kernel(float* __restrict__ out) {
    int r = blockIdx.x * 256 + threadIdx.x;
    float m = -INFINITY, s = 0.0f;
    #pragma unroll 4
    for (int nt = 0; nt < NTILES; ++nt) {
        float2 p = g_part[nt][r];
        float nm = fmaxf(m, p.x);
        s = s * __expf(m - nm) + p.y * __expf(p.x - nm);
        m = nm;
    }
    float z = m + logf(s);
    z = (z > 0.0f) ? z : 0.01f * z;
    z = (z > 0.0f) ? z : 0.01f * z;
    z = 0.5f * z * (1.0f + erff(z * 0.70710678118654752f));
    z = 0.5f * z * (1.0f + erff(z * 0.70710678118654752f));
    out[r] = z;
}

extern "C" void kernel_launch(void* const* d_in, const int* in_sizes, int n_in,
                              void* d_out, int out_size)
{
    const float* x    = (const float*)d_in[0];   // (M, K) f32 (widened fp16)
    const float* W    = (const float*)d_in[1];   // (K, N) f32
    const float* bias = (const float*)d_in[2];   // (N,)   f32
    float* out        = (float*)d_out;           // (M, 1) f32

    cudaFuncSetAttribute(gemm_lse_kernel,
                         cudaFuncAttributeMaxDynamicSharedMemorySize, SMEM_TOTAL);

    conv_x_kernel<<<(M_TOTAL * (size_t)K_TOTAL / 4) / 256, 256>>>(x);
    conv_wt_kernel<<<dim3(N_TOTAL / 32, K_TOTAL / 32), dim3(32, 8)>>>(W);
    gemm_lse_kernel<<<GRID, THREADS, SMEM_TOTAL>>>(bias);
    combine_kernel<<<M_TOTAL / 256, 256>>>(out);
}